// round 10
// baseline (speedup 1.0000x reference)
#include <cuda_runtime.h>

#define NB 16
#define L  1024
#define S  512
#define KW 3
#define KKTOT 1536

#define BM 128
#define BN 128
#define BK 16
#define TM 8
#define TN 8

#define ASTR (2*BM + 8)     // duplicated-A row stride (floats)
#define BSTR (16*10)        // chunked-B row stride: 16 chunks * 10 floats

// scratch (no runtime allocation allowed)
__device__ float g_M[(size_t)NB * L * S];      // 32 MB
__device__ float g_qbias[NB * L];
__device__ float g_rbias[NB * L];

typedef unsigned long long u64;

__device__ __forceinline__ u64 fma2(u64 a, u64 b, u64 c) {
    u64 d;
    asm("fma.rn.f32x2 %0, %1, %2, %3;" : "=l"(d) : "l"(a), "l"(b), "l"(c));
    return d;
}

// chunked B column mapping: logical float col c (0..127) -> physical offset
// (even for all even c, so float2/u64 8-byte accesses stay aligned)
__device__ __forceinline__ int bphys(int c) { return (c >> 3) * 10 + (c & 7); }

// ---------------------------------------------------------------------------
// Kernel 1: per-row biases.
// ---------------------------------------------------------------------------
__global__ void bias_kernel(const float* __restrict__ q, const float* __restrict__ k,
                            const float* __restrict__ bk, const float* __restrict__ Wb,
                            const float* __restrict__ bb, const float* __restrict__ bias_b) {
    int row  = blockIdx.x * (blockDim.x >> 5) + (threadIdx.x >> 5);
    int lane = threadIdx.x & 31;
    if (row >= NB * L) return;
    int b = row / L, j = row % L;
    const float* qrow = q + (size_t)row * S;
    float accq = 0.f, accr = 0.f;
    for (int c = lane; c < S; c += 32) {
        accq += qrow[c] * Wb[c];
        #pragma unroll
        for (int t = 0; t < KW; t++) {
            int jj = j + t - 1;
            if (jj >= 0 && jj < L)
                accr += bk[c * KW + t] * k[((size_t)b * L + jj) * S + c];
        }
    }
    #pragma unroll
    for (int o = 16; o > 0; o >>= 1) {
        accq += __shfl_xor_sync(0xffffffffu, accq, o);
        accr += __shfl_xor_sync(0xffffffffu, accr, o);
    }
    if (lane == 0) {
        g_qbias[row] = accq + bb[0];
        g_rbias[row] = accr + bias_b[0];
    }
}

// ---------------------------------------------------------------------------
// Kernel 2: M[b,j,qd] implicit-window SGEMM with packed f32x2 FMA.
// ---------------------------------------------------------------------------
__global__ __launch_bounds__(256, 2)
void mgemm_kernel(const float* __restrict__ kten, const float* __restrict__ Wk) {
    __shared__ __align__(16) float As2[BK][ASTR];
    __shared__ __align__(16) float Bsw[BK][BSTR];

    int b  = blockIdx.z;
    int n0 = blockIdx.x * BN;
    int m0 = blockIdx.y * BM;
    int tid = threadIdx.x;
    int tm = (tid >> 4) * TM;
    int cb = (tid & 15) * 10;          // B chunk base (phys floats)

    const float* kb = kten + (size_t)b * L * S;
    u64 acc2[TM][TN/2];
    #pragma unroll
    for (int i = 0; i < TM; i++)
        #pragma unroll
        for (int j = 0; j < TN/2; j++) acc2[i][j] = 0ULL;

    for (int kk0 = 0; kk0 < KKTOT; kk0 += BK) {
        int t  = kk0 / S;
        int c0 = kk0 % S;

        // A tile: 128 rows x 16 K, duplicated transposed store
        #pragma unroll
        for (int s = 0; s < 2; s++) {
            int idx = tid + 256 * s;
            int r   = idx >> 2;
            int kc  = (idx & 3) * 4;
            int jj  = m0 + r + t - 1;
            float4 v = make_float4(0.f, 0.f, 0.f, 0.f);
            if (jj >= 0 && jj < L)
                v = *reinterpret_cast<const float4*>(kb + (size_t)jj * S + c0 + kc);
            *reinterpret_cast<float2*>(&As2[kc + 0][2*r]) = make_float2(v.x, v.x);
            *reinterpret_cast<float2*>(&As2[kc + 1][2*r]) = make_float2(v.y, v.y);
            *reinterpret_cast<float2*>(&As2[kc + 2][2*r]) = make_float2(v.z, v.z);
            *reinterpret_cast<float2*>(&As2[kc + 3][2*r]) = make_float2(v.w, v.w);
        }
        // B tile: 16 K-rows x 128 cols, chunked layout, float2 stores (8B-aligned)
        #pragma unroll
        for (int s = 0; s < 2; s++) {
            int idx = tid + 256 * s;
            int r   = idx >> 5;
            int nc  = (idx & 31) * 4;
            int rW  = (c0 + r) * KW + t;
            float4 v = *reinterpret_cast<const float4*>(Wk + (size_t)rW * S + n0 + nc);
            int p0 = bphys(nc);          // even
            int p1 = bphys(nc + 2);      // even
            *reinterpret_cast<float2*>(&Bsw[r][p0]) = make_float2(v.x, v.y);
            *reinterpret_cast<float2*>(&Bsw[r][p1]) = make_float2(v.z, v.w);
        }
        __syncthreads();

        #pragma unroll
        for (int kc = 0; kc < BK; kc++) {
            u64 a2[TM], b2[TN/2];
            #pragma unroll
            for (int i = 0; i < TM; i++)
                a2[i] = *reinterpret_cast<const u64*>(&As2[kc][2*(tm + i)]);
            #pragma unroll
            for (int j = 0; j < TN/2; j++)
                b2[j] = *reinterpret_cast<const u64*>(&Bsw[kc][cb + 2*j]);
            #pragma unroll
            for (int i = 0; i < TM; i++)
                #pragma unroll
                for (int j = 0; j < TN/2; j++)
                    acc2[i][j] = fma2(a2[i], b2[j], acc2[i][j]);
        }
        __syncthreads();
    }

    float* Mb = g_M + (size_t)b * L * S;
    int tn = (tid & 15) * TN;
    #pragma unroll
    for (int i = 0; i < TM; i++) {
        float2 p0 = *reinterpret_cast<float2*>(&acc2[i][0]);
        float2 p1 = *reinterpret_cast<float2*>(&acc2[i][1]);
        float2 p2 = *reinterpret_cast<float2*>(&acc2[i][2]);
        float2 p3 = *reinterpret_cast<float2*>(&acc2[i][3]);
        float4 v0 = make_float4(p0.x, p0.y, p1.x, p1.y);
        float4 v1 = make_float4(p2.x, p2.y, p3.x, p3.y);
        float* row = Mb + (size_t)(m0 + tm + i) * S + n0 + tn;
        *reinterpret_cast<float4*>(row + 0) = v0;
        *reinterpret_cast<float4*>(row + 4) = v1;
    }
}

// ---------------------------------------------------------------------------
// Kernel 3: scores = q @ M^T + biases, packed f32x2 FMA.
// ---------------------------------------------------------------------------
__global__ __launch_bounds__(256, 2)
void score_kernel(const float* __restrict__ q, float* __restrict__ out) {
    __shared__ __align__(16) float As2[BK][ASTR];
    __shared__ __align__(16) float Bsw[BK][BSTR];

    int b  = blockIdx.z;
    int n0 = blockIdx.x * BN;
    int m0 = blockIdx.y * BM;
    int tid = threadIdx.x;
    int tm = (tid >> 4) * TM;
    int cb = (tid & 15) * 10;

    const float* qa = q   + ((size_t)b * L + m0) * S;
    const float* Mb = g_M + ((size_t)b * L + n0) * S;
    u64 acc2[TM][TN/2];
    #pragma unroll
    for (int i = 0; i < TM; i++)
        #pragma unroll
        for (int j = 0; j < TN/2; j++) acc2[i][j] = 0ULL;

    for (int k0 = 0; k0 < S; k0 += BK) {
        // A tile (q): duplicated transposed store
        #pragma unroll
        for (int s = 0; s < 2; s++) {
            int idx = tid + 256 * s;
            int r   = idx >> 2;
            int kc  = (idx & 3) * 4;
            float4 v = *reinterpret_cast<const float4*>(qa + (size_t)r * S + k0 + kc);
            *reinterpret_cast<float2*>(&As2[kc + 0][2*r]) = make_float2(v.x, v.x);
            *reinterpret_cast<float2*>(&As2[kc + 1][2*r]) = make_float2(v.y, v.y);
            *reinterpret_cast<float2*>(&As2[kc + 2][2*r]) = make_float2(v.z, v.z);
            *reinterpret_cast<float2*>(&As2[kc + 3][2*r]) = make_float2(v.w, v.w);
        }
        // B tile (M, NT): transposed scalar store into chunked layout
        #pragma unroll
        for (int s = 0; s < 2; s++) {
            int idx = tid + 256 * s;
            int r   = idx >> 2;                 // j column 0..127
            int kc  = (idx & 3) * 4;
            float4 v = *reinterpret_cast<const float4*>(Mb + (size_t)r * S + k0 + kc);
            int p = bphys(r);
            Bsw[kc + 0][p] = v.x;
            Bsw[kc + 1][p] = v.y;
            Bsw[kc + 2][p] = v.z;
            Bsw[kc + 3][p] = v.w;
        }
        __syncthreads();

        #pragma unroll
        for (int kc = 0; kc < BK; kc++) {
            u64 a2[TM], b2[TN/2];
            #pragma unroll
            for (int i = 0; i < TM; i++)
                a2[i] = *reinterpret_cast<const u64*>(&As2[kc][2*(tm + i)]);
            #pragma unroll
            for (int j = 0; j < TN/2; j++)
                b2[j] = *reinterpret_cast<const u64*>(&Bsw[kc][cb + 2*j]);
            #pragma unroll
            for (int i = 0; i < TM; i++)
                #pragma unroll
                for (int j = 0; j < TN/2; j++)
                    acc2[i][j] = fma2(a2[i], b2[j], acc2[i][j]);
        }
        __syncthreads();
    }

    int tn = (tid & 15) * TN;
    float rb[TN];
    #pragma unroll
    for (int jx = 0; jx < TN; jx++) rb[jx] = g_rbias[b * L + n0 + tn + jx];

    #pragma unroll
    for (int i = 0; i < TM; i++) {
        float qb = g_qbias[b * L + m0 + tm + i];
        float2 p[4];
        #pragma unroll
        for (int j = 0; j < 4; j++) p[j] = *reinterpret_cast<float2*>(&acc2[i][j]);
        float* orow = out + ((size_t)b * L + (m0 + tm + i)) * L + n0 + tn;
        float4 v0 = make_float4(p[0].x + qb + rb[0], p[0].y + qb + rb[1],
                                p[1].x + qb + rb[2], p[1].y + qb + rb[3]);
        float4 v1 = make_float4(p[2].x + qb + rb[4], p[2].y + qb + rb[5],
                                p[3].x + qb + rb[6], p[3].y + qb + rb[7]);
        *reinterpret_cast<float4*>(orow + 0) = v0;
        *reinterpret_cast<float4*>(orow + 4) = v1;
    }
}

// ---------------------------------------------------------------------------
extern "C" void kernel_launch(void* const* d_in, const int* in_sizes, int n_in,
                              void* d_out, int out_size) {
    const float* q      = (const float*)d_in[0];
    const float* k      = (const float*)d_in[1];
    const float* Wk     = (const float*)d_in[2];
    const float* bk     = (const float*)d_in[3];
    const float* Wb     = (const float*)d_in[4];
    const float* bb     = (const float*)d_in[5];
    const float* bias_b = (const float*)d_in[6];
    float* out = (float*)d_out;

    bias_kernel<<<(NB * L) / 8, 256>>>(q, k, bk, Wb, bb, bias_b);

    dim3 g2(S / BN, L / BM, NB);
    mgemm_kernel<<<g2, 256>>>(k, Wk);

    dim3 g3(L / BN, L / BM, NB);
    score_kernel<<<g3, 256>>>(q, out);
}

// round 11
// speedup vs baseline: 1.0021x; 1.0021x over previous
#include <cuda_runtime.h>

#define NB 16
#define L  1024
#define S  512
#define KW 3
#define KKTOT 1536

#define BM 128
#define BN 128
#define BK 16
#define TM 8
#define TN 8

#define ASTR (2*BM + 8)     // duplicated-A row stride (floats)
#define BSTR (16*10)        // chunked-B row stride: 16 chunks * 10 floats

// scratch (no runtime allocation allowed)
__device__ float g_M[(size_t)NB * L * S];      // 32 MB
__device__ float g_qbias[NB * L];
__device__ float g_rbias[NB * L];

typedef unsigned long long u64;

__device__ __forceinline__ u64 fma2(u64 a, u64 b, u64 c) {
    u64 d;
    asm("fma.rn.f32x2 %0, %1, %2, %3;" : "=l"(d) : "l"(a), "l"(b), "l"(c));
    return d;
}

// chunked B column mapping: logical float col c (0..127) -> physical offset
// (even for all even c, so float2/u64 8-byte accesses stay aligned)
__device__ __forceinline__ int bphys(int c) { return (c >> 3) * 10 + (c & 7); }

// ---------------------------------------------------------------------------
// Kernel 1: per-row biases.
// ---------------------------------------------------------------------------
__global__ void bias_kernel(const float* __restrict__ q, const float* __restrict__ k,
                            const float* __restrict__ bk, const float* __restrict__ Wb,
                            const float* __restrict__ bb, const float* __restrict__ bias_b) {
    int row  = blockIdx.x * (blockDim.x >> 5) + (threadIdx.x >> 5);
    int lane = threadIdx.x & 31;
    if (row >= NB * L) return;
    int b = row / L, j = row % L;
    const float* qrow = q + (size_t)row * S;
    float accq = 0.f, accr = 0.f;
    for (int c = lane; c < S; c += 32) {
        accq += qrow[c] * Wb[c];
        #pragma unroll
        for (int t = 0; t < KW; t++) {
            int jj = j + t - 1;
            if (jj >= 0 && jj < L)
                accr += bk[c * KW + t] * k[((size_t)b * L + jj) * S + c];
        }
    }
    #pragma unroll
    for (int o = 16; o > 0; o >>= 1) {
        accq += __shfl_xor_sync(0xffffffffu, accq, o);
        accr += __shfl_xor_sync(0xffffffffu, accr, o);
    }
    if (lane == 0) {
        g_qbias[row] = accq + bb[0];
        g_rbias[row] = accr + bias_b[0];
    }
}

// ---------------------------------------------------------------------------
// Kernel 2: M[b,j,qd] implicit-window SGEMM with packed f32x2 FMA.
// ---------------------------------------------------------------------------
__global__ __launch_bounds__(256, 2)
void mgemm_kernel(const float* __restrict__ kten, const float* __restrict__ Wk) {
    __shared__ __align__(16) float As2[BK][ASTR];
    __shared__ __align__(16) float Bsw[BK][BSTR];

    int b  = blockIdx.z;
    int n0 = blockIdx.x * BN;
    int m0 = blockIdx.y * BM;
    int tid = threadIdx.x;
    int tm = (tid >> 4) * TM;
    int cb = (tid & 15) * 10;          // B chunk base (phys floats)

    const float* kb = kten + (size_t)b * L * S;
    u64 acc2[TM][TN/2];
    #pragma unroll
    for (int i = 0; i < TM; i++)
        #pragma unroll
        for (int j = 0; j < TN/2; j++) acc2[i][j] = 0ULL;

    for (int kk0 = 0; kk0 < KKTOT; kk0 += BK) {
        int t  = kk0 / S;
        int c0 = kk0 % S;

        // A tile: 128 rows x 16 K, duplicated transposed store
        #pragma unroll
        for (int s = 0; s < 2; s++) {
            int idx = tid + 256 * s;
            int r   = idx >> 2;
            int kc  = (idx & 3) * 4;
            int jj  = m0 + r + t - 1;
            float4 v = make_float4(0.f, 0.f, 0.f, 0.f);
            if (jj >= 0 && jj < L)
                v = *reinterpret_cast<const float4*>(kb + (size_t)jj * S + c0 + kc);
            *reinterpret_cast<float2*>(&As2[kc + 0][2*r]) = make_float2(v.x, v.x);
            *reinterpret_cast<float2*>(&As2[kc + 1][2*r]) = make_float2(v.y, v.y);
            *reinterpret_cast<float2*>(&As2[kc + 2][2*r]) = make_float2(v.z, v.z);
            *reinterpret_cast<float2*>(&As2[kc + 3][2*r]) = make_float2(v.w, v.w);
        }
        // B tile: 16 K-rows x 128 cols, chunked layout, float2 stores (8B-aligned)
        #pragma unroll
        for (int s = 0; s < 2; s++) {
            int idx = tid + 256 * s;
            int r   = idx >> 5;
            int nc  = (idx & 31) * 4;
            int rW  = (c0 + r) * KW + t;
            float4 v = *reinterpret_cast<const float4*>(Wk + (size_t)rW * S + n0 + nc);
            int p0 = bphys(nc);          // even
            int p1 = bphys(nc + 2);      // even
            *reinterpret_cast<float2*>(&Bsw[r][p0]) = make_float2(v.x, v.y);
            *reinterpret_cast<float2*>(&Bsw[r][p1]) = make_float2(v.z, v.w);
        }
        __syncthreads();

        #pragma unroll
        for (int kc = 0; kc < BK; kc++) {
            u64 a2[TM], b2[TN/2];
            #pragma unroll
            for (int i = 0; i < TM; i++)
                a2[i] = *reinterpret_cast<const u64*>(&As2[kc][2*(tm + i)]);
            #pragma unroll
            for (int j = 0; j < TN/2; j++)
                b2[j] = *reinterpret_cast<const u64*>(&Bsw[kc][cb + 2*j]);
            #pragma unroll
            for (int i = 0; i < TM; i++)
                #pragma unroll
                for (int j = 0; j < TN/2; j++)
                    acc2[i][j] = fma2(a2[i], b2[j], acc2[i][j]);
        }
        __syncthreads();
    }

    float* Mb = g_M + (size_t)b * L * S;
    int tn = (tid & 15) * TN;
    #pragma unroll
    for (int i = 0; i < TM; i++) {
        float2 p0 = *reinterpret_cast<float2*>(&acc2[i][0]);
        float2 p1 = *reinterpret_cast<float2*>(&acc2[i][1]);
        float2 p2 = *reinterpret_cast<float2*>(&acc2[i][2]);
        float2 p3 = *reinterpret_cast<float2*>(&acc2[i][3]);
        float4 v0 = make_float4(p0.x, p0.y, p1.x, p1.y);
        float4 v1 = make_float4(p2.x, p2.y, p3.x, p3.y);
        float* row = Mb + (size_t)(m0 + tm + i) * S + n0 + tn;
        *reinterpret_cast<float4*>(row + 0) = v0;
        *reinterpret_cast<float4*>(row + 4) = v1;
    }
}

// ---------------------------------------------------------------------------
// Kernel 3: scores = q @ M^T + biases, packed f32x2 FMA.
// ---------------------------------------------------------------------------
__global__ __launch_bounds__(256, 2)
void score_kernel(const float* __restrict__ q, float* __restrict__ out) {
    __shared__ __align__(16) float As2[BK][ASTR];
    __shared__ __align__(16) float Bsw[BK][BSTR];

    int b  = blockIdx.z;
    int n0 = blockIdx.x * BN;
    int m0 = blockIdx.y * BM;
    int tid = threadIdx.x;
    int tm = (tid >> 4) * TM;
    int cb = (tid & 15) * 10;

    const float* qa = q   + ((size_t)b * L + m0) * S;
    const float* Mb = g_M + ((size_t)b * L + n0) * S;
    u64 acc2[TM][TN/2];
    #pragma unroll
    for (int i = 0; i < TM; i++)
        #pragma unroll
        for (int j = 0; j < TN/2; j++) acc2[i][j] = 0ULL;

    for (int k0 = 0; k0 < S; k0 += BK) {
        // A tile (q): duplicated transposed store
        #pragma unroll
        for (int s = 0; s < 2; s++) {
            int idx = tid + 256 * s;
            int r   = idx >> 2;
            int kc  = (idx & 3) * 4;
            float4 v = *reinterpret_cast<const float4*>(qa + (size_t)r * S + k0 + kc);
            *reinterpret_cast<float2*>(&As2[kc + 0][2*r]) = make_float2(v.x, v.x);
            *reinterpret_cast<float2*>(&As2[kc + 1][2*r]) = make_float2(v.y, v.y);
            *reinterpret_cast<float2*>(&As2[kc + 2][2*r]) = make_float2(v.z, v.z);
            *reinterpret_cast<float2*>(&As2[kc + 3][2*r]) = make_float2(v.w, v.w);
        }
        // B tile (M, NT): transposed scalar store into chunked layout
        #pragma unroll
        for (int s = 0; s < 2; s++) {
            int idx = tid + 256 * s;
            int r   = idx >> 2;                 // j column 0..127
            int kc  = (idx & 3) * 4;
            float4 v = *reinterpret_cast<const float4*>(Mb + (size_t)r * S + k0 + kc);
            int p = bphys(r);
            Bsw[kc + 0][p] = v.x;
            Bsw[kc + 1][p] = v.y;
            Bsw[kc + 2][p] = v.z;
            Bsw[kc + 3][p] = v.w;
        }
        __syncthreads();

        #pragma unroll
        for (int kc = 0; kc < BK; kc++) {
            u64 a2[TM], b2[TN/2];
            #pragma unroll
            for (int i = 0; i < TM; i++)
                a2[i] = *reinterpret_cast<const u64*>(&As2[kc][2*(tm + i)]);
            #pragma unroll
            for (int j = 0; j < TN/2; j++)
                b2[j] = *reinterpret_cast<const u64*>(&Bsw[kc][cb + 2*j]);
            #pragma unroll
            for (int i = 0; i < TM; i++)
                #pragma unroll
                for (int j = 0; j < TN/2; j++)
                    acc2[i][j] = fma2(a2[i], b2[j], acc2[i][j]);
        }
        __syncthreads();
    }

    int tn = (tid & 15) * TN;
    float rb[TN];
    #pragma unroll
    for (int jx = 0; jx < TN; jx++) rb[jx] = g_rbias[b * L + n0 + tn + jx];

    #pragma unroll
    for (int i = 0; i < TM; i++) {
        float qb = g_qbias[b * L + m0 + tm + i];
        float2 p[4];
        #pragma unroll
        for (int j = 0; j < 4; j++) p[j] = *reinterpret_cast<float2*>(&acc2[i][j]);
        float* orow = out + ((size_t)b * L + (m0 + tm + i)) * L + n0 + tn;
        float4 v0 = make_float4(p[0].x + qb + rb[0], p[0].y + qb + rb[1],
                                p[1].x + qb + rb[2], p[1].y + qb + rb[3]);
        float4 v1 = make_float4(p[2].x + qb + rb[4], p[2].y + qb + rb[5],
                                p[3].x + qb + rb[6], p[3].y + qb + rb[7]);
        *reinterpret_cast<float4*>(orow + 0) = v0;
        *reinterpret_cast<float4*>(orow + 4) = v1;
    }
}

// ---------------------------------------------------------------------------
extern "C" void kernel_launch(void* const* d_in, const int* in_sizes, int n_in,
                              void* d_out, int out_size) {
    const float* q      = (const float*)d_in[0];
    const float* k      = (const float*)d_in[1];
    const float* Wk     = (const float*)d_in[2];
    const float* bk     = (const float*)d_in[3];
    const float* Wb     = (const float*)d_in[4];
    const float* bb     = (const float*)d_in[5];
    const float* bias_b = (const float*)d_in[6];
    float* out = (float*)d_out;

    bias_kernel<<<(NB * L) / 8, 256>>>(q, k, bk, Wb, bb, bias_b);

    dim3 g2(S / BN, L / BM, NB);
    mgemm_kernel<<<g2, 256>>>(k, Wk);

    dim3 g3(L / BN, L / BM, NB);
    score_kernel<<<g3, 256>>>(q, out);
}